// round 5
// baseline (speedup 1.0000x reference)
#include <cuda_runtime.h>
#include <cstdint>

#define BATCH 131072
#define NF    64
#define RPW   8            // rows per warp (4 pairs; 16-lane subwarp per row)
#define WARPS_PER_BLOCK 8  // 256 threads

// smem: per warp, 8 rows x (p,q) x 16 lanes x float4 = 4KB -> 32KB/block
__global__ __launch_bounds__(256) void svd_predict_kernel(
    const int*   __restrict__ user_item,   // [BATCH, 2]
    const float* __restrict__ pu,          // [N_USERS, 64]
    const float* __restrict__ qi,          // [N_ITEMS, 64]
    const float* __restrict__ bu,          // [N_USERS]
    const float* __restrict__ bi,          // [N_ITEMS]
    const float* __restrict__ gmean,       // [1]
    float*       __restrict__ out)         // [BATCH] pred ++ [BATCH,128] feat
{
    __shared__ float4 buf[WARPS_PER_BLOCK][RPW][2][16];

    const int warp_in_blk = threadIdx.x >> 5;
    const int warp_id     = blockIdx.x * WARPS_PER_BLOCK + warp_in_blk;
    const int lane        = threadIdx.x & 31;
    const int half        = lane >> 4;      // which row of each pair
    const int sub         = lane & 15;      // lane within 16-lane subwarp
    const int row0        = warp_id * RPW + half;   // rows: row0 + 2*i

    // ---- batch index loads (1MB array, L2 resident) ----
    int2 ids[4];
    #pragma unroll
    for (int i = 0; i < 4; ++i)
        ids[i] = __ldg(((const int2*)user_item) + row0 + 2 * i);

    // ---- issue 8 register-free async gathers per lane (max MLP, no reg cost) ----
    #pragma unroll
    for (int i = 0; i < 4; ++i) {
        const int r = 2 * i + half;
        uint32_t dp = (uint32_t)__cvta_generic_to_shared(&buf[warp_in_blk][r][0][sub]);
        uint32_t dq = (uint32_t)__cvta_generic_to_shared(&buf[warp_in_blk][r][1][sub]);
        const float4* sp = ((const float4*)(pu + (size_t)ids[i].x * NF)) + sub;
        const float4* sq = ((const float4*)(qi + (size_t)ids[i].y * NF)) + sub;
        asm volatile("cp.async.cg.shared.global [%0], [%1], 16;\n" :: "r"(dp), "l"(sp));
        asm volatile("cp.async.cg.shared.global [%0], [%1], 16;\n" :: "r"(dq), "l"(sq));
    }
    asm volatile("cp.async.commit_group;\n");

    // ---- bias gathers overlap with the async copies ----
    float bsum[4];
    #pragma unroll
    for (int i = 0; i < 4; ++i)
        if (sub == 0)
            bsum[i] = __ldg(bu + ids[i].x) + __ldg(bi + ids[i].y);
    const float gm = __ldg(gmean);

    asm volatile("cp.async.wait_group 0;\n");
    // Each lane reads only the bytes it copied itself -> no barrier needed.

    #pragma unroll
    for (int i = 0; i < 4; ++i) {
        const int r   = 2 * i + half;
        const int row = row0 + 2 * i;

        const float4 p = buf[warp_in_blk][r][0][sub];
        const float4 q = buf[warp_in_blk][r][1][sub];

        float partial = p.x * q.x + p.y * q.y + p.z * q.z + p.w * q.w;
        #pragma unroll
        for (int off = 8; off > 0; off >>= 1)
            partial += __shfl_xor_sync(0xffffffffu, partial, off, 16);

        // features: [p(64) | q(64)] = 32 float4, streaming stores
        float4* frow = (float4*)(out + (size_t)BATCH + (size_t)row * (2 * NF));
        __stcs(frow + sub,      p);
        __stcs(frow + sub + 16, q);

        if (sub == 0) {
            float v = gm + bsum[i] + partial;
            v = fminf(fmaxf(v, 1.0f), 5.0f);
            __stcs(out + row, v);
        }
    }
}

extern "C" void kernel_launch(void* const* d_in, const int* in_sizes, int n_in,
                              void* d_out, int out_size)
{
    const int*   user_item = (const int*)  d_in[0];
    const float* pu        = (const float*)d_in[1];
    const float* qi        = (const float*)d_in[2];
    const float* bu        = (const float*)d_in[3];
    const float* bi        = (const float*)d_in[4];
    const float* gmean     = (const float*)d_in[5];
    float*       out       = (float*)d_out;

    const int rows_per_block = WARPS_PER_BLOCK * RPW;   // 64
    const int grid = (BATCH + rows_per_block - 1) / rows_per_block;  // 2048
    svd_predict_kernel<<<grid, 256>>>(user_item, pu, qi, bu, bi, gmean, out);
}

// round 6
// speedup vs baseline: 1.0264x; 1.0264x over previous
#include <cuda_runtime.h>
#include <cstdint>

#define BATCH 131072
#define NF    64
#define RPW   8   // rows per warp (4 pairs; 16-lane subwarp per row)

__global__ __launch_bounds__(256, 6) void svd_predict_kernel(
    const int*   __restrict__ user_item,   // [BATCH, 2]
    const float* __restrict__ pu,          // [N_USERS, 64]
    const float* __restrict__ qi,          // [N_ITEMS, 64]
    const float* __restrict__ bu,          // [N_USERS]
    const float* __restrict__ bi,          // [N_ITEMS]
    const float* __restrict__ gmean,       // [1]
    float*       __restrict__ out)         // [BATCH] pred ++ [BATCH,128] feat
{
    const int warp_id = (blockIdx.x * blockDim.x + threadIdx.x) >> 5;
    const int lane    = threadIdx.x & 31;
    const int half    = lane >> 4;        // which row of the pair
    const int sub     = lane & 15;        // lane within 16-lane subwarp
    const int row0    = warp_id * RPW + half;   // rows: row0 + 2*i, i=0..3

    // ---- batch all index loads (1MB array, L2 resident) ----
    int2 ids[4];
    #pragma unroll
    for (int i = 0; i < 4; ++i)
        ids[i] = __ldg(((const int2*)user_item) + row0 + 2 * i);

    // ---- issue all 8 independent 16B embedding loads back-to-back (max MLP).
    //      __ldcs: rows are ~single-use, evict-first keeps L2 for ids/biases.
    float4 p[4], q[4];
    #pragma unroll
    for (int i = 0; i < 4; ++i) {
        p[i] = __ldcs(((const float4*)(pu + (size_t)ids[i].x * NF)) + sub);
        q[i] = __ldcs(((const float4*)(qi + (size_t)ids[i].y * NF)) + sub);
    }

    // ---- bias gathers (small tables, L2-resident) overlap the row loads ----
    float bsum[4];
    #pragma unroll
    for (int i = 0; i < 4; ++i)
        if (sub == 0)
            bsum[i] = __ldg(bu + ids[i].x) + __ldg(bi + ids[i].y);

    const float gm = __ldg(gmean);

    // ---- per-row: dot, 16-lane reduce, streaming stores ----
    #pragma unroll
    for (int i = 0; i < 4; ++i) {
        const int row = row0 + 2 * i;

        float partial = p[i].x * q[i].x + p[i].y * q[i].y
                      + p[i].z * q[i].z + p[i].w * q[i].w;
        #pragma unroll
        for (int off = 8; off > 0; off >>= 1)
            partial += __shfl_xor_sync(0xffffffffu, partial, off, 16);

        // features: [p(64) | q(64)] = 32 float4 per row
        float4* frow = (float4*)(out + (size_t)BATCH + (size_t)row * (2 * NF));
        __stcs(frow + sub,      p[i]);
        __stcs(frow + sub + 16, q[i]);

        if (sub == 0) {
            float v = gm + bsum[i] + partial;
            v = fminf(fmaxf(v, 1.0f), 5.0f);
            __stcs(out + row, v);
        }
    }
}

extern "C" void kernel_launch(void* const* d_in, const int* in_sizes, int n_in,
                              void* d_out, int out_size)
{
    const int*   user_item = (const int*)  d_in[0];
    const float* pu        = (const float*)d_in[1];
    const float* qi        = (const float*)d_in[2];
    const float* bu        = (const float*)d_in[3];
    const float* bi        = (const float*)d_in[4];
    const float* gmean     = (const float*)d_in[5];
    float*       out       = (float*)d_out;

    const int rows_per_block = (256 / 32) * RPW;   // 64
    const int grid = (BATCH + rows_per_block - 1) / rows_per_block;  // 2048
    svd_predict_kernel<<<grid, 256>>>(user_item, pu, qi, bu, bi, gmean, out);
}

// round 7
// speedup vs baseline: 1.2900x; 1.2568x over previous
#include <cuda_runtime.h>
#include <cstdint>

#define BATCH 131072
#define NF    64
#define RPW   8   // rows per warp (4 pairs; 16-lane subwarp per row)

__global__ __launch_bounds__(256, 6) void svd_predict_kernel(
    const int*   __restrict__ user_item,   // [BATCH, 2]
    const float* __restrict__ pu,          // [N_USERS, 64]
    const float* __restrict__ qi,          // [N_ITEMS, 64]
    const float* __restrict__ bu,          // [N_USERS]
    const float* __restrict__ bi,          // [N_ITEMS]
    const float* __restrict__ gmean,       // [1]
    float*       __restrict__ out)         // [BATCH] pred ++ [BATCH,128] feat
{
    const int warp_id = (blockIdx.x * blockDim.x + threadIdx.x) >> 5;
    const int lane    = threadIdx.x & 31;
    const int half    = lane >> 4;        // which row of the pair
    const int sub     = lane & 15;        // lane within 16-lane subwarp
    const int row0    = warp_id * RPW + half;   // rows: row0 + 2*i, i=0..3

    // ---- batch all index loads (1MB array, L2 resident) ----
    int2 ids[4];
    #pragma unroll
    for (int i = 0; i < 4; ++i)
        ids[i] = __ldg(((const int2*)user_item) + row0 + 2 * i);

    // ---- issue all 8 independent 16B embedding loads back-to-back (max MLP).
    //      Default caching: touched rows (~67MB) fit in L2, duplicates + sector
    //      sharing + cross-replay residency give real reuse (R6 lesson).
    float4 p[4], q[4];
    #pragma unroll
    for (int i = 0; i < 4; ++i) {
        p[i] = __ldg(((const float4*)(pu + (size_t)ids[i].x * NF)) + sub);
        q[i] = __ldg(((const float4*)(qi + (size_t)ids[i].y * NF)) + sub);
    }

    // ---- bias gathers (small tables, L2-resident) overlap the row loads ----
    float bsum[4];
    #pragma unroll
    for (int i = 0; i < 4; ++i)
        if (sub == 0)
            bsum[i] = __ldg(bu + ids[i].x) + __ldg(bi + ids[i].y);

    const float gm = __ldg(gmean);

    // ---- per-row: dot, 16-lane reduce, streaming stores ----
    #pragma unroll
    for (int i = 0; i < 4; ++i) {
        const int row = row0 + 2 * i;

        float partial = p[i].x * q[i].x + p[i].y * q[i].y
                      + p[i].z * q[i].z + p[i].w * q[i].w;
        #pragma unroll
        for (int off = 8; off > 0; off >>= 1)
            partial += __shfl_xor_sync(0xffffffffu, partial, off, 16);

        // features: [p(64) | q(64)] = 32 float4 per row (write-once stream)
        float4* frow = (float4*)(out + (size_t)BATCH + (size_t)row * (2 * NF));
        __stcs(frow + sub,      p[i]);
        __stcs(frow + sub + 16, q[i]);

        if (sub == 0) {
            float v = gm + bsum[i] + partial;
            v = fminf(fmaxf(v, 1.0f), 5.0f);
            __stcs(out + row, v);
        }
    }
}

extern "C" void kernel_launch(void* const* d_in, const int* in_sizes, int n_in,
                              void* d_out, int out_size)
{
    const int*   user_item = (const int*)  d_in[0];
    const float* pu        = (const float*)d_in[1];
    const float* qi        = (const float*)d_in[2];
    const float* bu        = (const float*)d_in[3];
    const float* bi        = (const float*)d_in[4];
    const float* gmean     = (const float*)d_in[5];
    float*       out       = (float*)d_out;

    const int rows_per_block = (256 / 32) * RPW;   // 64
    const int grid = (BATCH + rows_per_block - 1) / rows_per_block;  // 2048
    svd_predict_kernel<<<grid, 256>>>(user_item, pu, qi, bu, bi, gmean, out);
}